// round 10
// baseline (speedup 1.0000x reference)
#include <cuda_runtime.h>
#include <math_constants.h>

#define DIMD 256
#define NTOK 4096
#define BATCH 4
#define ROWS_TOTAL (BATCH * NTOK)
#define ATT_SCALE 0.17677669529663687f
#define THRESH 0.6f

#define KC 16              // k-chunk depth
#define AP 260             // A dup tile pitch (words per k-row): 2*128 + 4 pad
#define BP 132             // B tile pitch (words per k-row): 128 + 4 pad
#define AW (KC * AP)       // 4160 words per A buffer
#define BW (KC * BP)       // 2112 words per B buffer
#define SMEM_BYTES ((2 * AW + 2 * BW) * 4)   // 50176 B

typedef unsigned long long ull;

// ---------------- scratch (device globals; no allocation allowed) -------------
__device__ float g_q[ROWS_TOTAL * DIMD];
__device__ float g_k[ROWS_TOTAL * DIMD];
__device__ float g_z[ROWS_TOTAL * DIMD];
__device__ float g_M[DIMD * DIMD];
__device__ float g_p[ROWS_TOTAL];
__device__ int   g_j[ROWS_TOTAL];

// ---------------- f32x2 helpers ----------------------------------------------
__device__ __forceinline__ void fma2(ull &d, ull a, ull b) {
    asm("fma.rn.f32x2 %0, %1, %2, %0;" : "+l"(d) : "l"(a), "l"(b));
}
__device__ __forceinline__ float2 unpack2(ull v) {
    unsigned lo, hi;
    asm("mov.b64 {%0, %1}, %2;" : "=r"(lo), "=r"(hi) : "l"(v));
    return make_float2(__uint_as_float(lo), __uint_as_float(hi));
}

// ============ tile layouts ====================================================
// A tile (dup): KC k-rows x 260 words. Row r (0..127) of dim k stored as the
//   duplicated pair {a,a} at word  k*AP + 2*r.
// B tile: KC k-rows x 132 words. Col c at word k*BP + c.

// ---- stores: regs -> smem (512-thread mappings)
// T-pattern loader: row/col = tid>>2 (0..127), k4 = tid&3 (4 dims each)
__device__ __forceinline__ void sts_A_dup(float* dst, float4 v, int tid) {
    int row = tid >> 2, k4 = tid & 3;
    float* d = dst + (4 * k4) * AP + 2 * row;
    *(float2*)(d         ) = make_float2(v.x, v.x);
    *(float2*)(d + AP    ) = make_float2(v.y, v.y);
    *(float2*)(d + 2 * AP) = make_float2(v.z, v.z);
    *(float2*)(d + 3 * AP) = make_float2(v.w, v.w);
}
__device__ __forceinline__ void sts_B_fromT(float* dst, float4 v, int tid) {
    int col = tid >> 2, k4 = tid & 3;
    float* d = dst + (4 * k4) * BP + col;
    d[0]      = v.x;
    d[BP]     = v.y;
    d[2 * BP] = v.z;
    d[3 * BP] = v.w;
}
// N-pattern loader (weights): kr = tid>>5 (0..15), c4 = tid&31 (4 cols each)
__device__ __forceinline__ void sts_B_fromN(float* dst, float4 v, int tid) {
    int kr = tid >> 5, c4 = tid & 31;
    *(float4*)(dst + kr * BP + 4 * c4) = v;
}

// ---- one k-step: 4 rows x 8 cols per thread, f32x2
__device__ __forceinline__ void mma_step(const float* __restrict__ as_,
                                         const float* __restrict__ bs_,
                                         int k, int tx, int ty, ull acc[4][4]) {
    const float* kr = bs_ + k * BP + 2 * tx;
    ull B[4];
    B[0] = *(const ull*)(kr     );
    B[1] = *(const ull*)(kr + 32);
    B[2] = *(const ull*)(kr + 64);
    B[3] = *(const ull*)(kr + 96);

    const float* qr = as_ + k * AP + 8 * ty;
    ulonglong2 A01 = *(const ulonglong2*)(qr);
    ulonglong2 A23 = *(const ulonglong2*)(qr + 4);
    ull A[4] = { A01.x, A01.y, A23.x, A23.y };
#pragma unroll
    for (int r = 0; r < 4; r++)
#pragma unroll
        for (int c = 0; c < 4; c++)
            fma2(acc[r][c], A[r], B[c]);
}

// ---------------- tiled GEMM: C[M x 256] = A[M x 256] @ B[256 x 256] (+bias) --
__global__ __launch_bounds__(512) void gemm_kernel(const float* __restrict__ A,
                                                   const float* __restrict__ B,
                                                   float* __restrict__ C,
                                                   const float* __restrict__ bias,
                                                   int hasBias) {
    extern __shared__ float sm[];
    float* as_ = sm;                  // 2 * AW
    float* bs_ = sm + 2 * AW;         // 2 * BW
    int tid = threadIdx.x, tx = tid & 15, ty = tid >> 4;
    int rb = blockIdx.x * 128, cb = blockIdx.y * 128;

    int arow = tid >> 2, ak4 = tid & 3;       // A T-loader coords
    int bkr = tid >> 5, bc4 = tid & 31;       // B N-loader coords

    ull acc[4][4];
#pragma unroll
    for (int r = 0; r < 4; r++)
#pragma unroll
        for (int c = 0; c < 4; c++) acc[r][c] = 0ULL;

    const float* Abase = A + (size_t)(rb + arow) * DIMD + ak4 * 4;
    const float* Bbase = B + (size_t)bkr * DIMD + cb + 4 * bc4;

    float4 va = *(const float4*)(Abase);
    float4 vb = *(const float4*)(Bbase);
    sts_A_dup(as_, va, tid);
    sts_B_fromN(bs_, vb, tid);
    __syncthreads();

    int p = 0;
    for (int it = 0; it < DIMD / KC; it++) {
        int nit = it + 1;
        if (nit < DIMD / KC) {
            va = *(const float4*)(Abase + nit * KC);
            vb = *(const float4*)(Bbase + (size_t)nit * KC * DIMD);
        }
        const float* ap = as_ + p * AW;
        const float* bpp = bs_ + p * BW;
#pragma unroll
        for (int k = 0; k < KC; k++) mma_step(ap, bpp, k, tx, ty, acc);
        if (nit < DIMD / KC) {
            sts_A_dup(as_ + (p ^ 1) * AW, va, tid);
            sts_B_fromN(bs_ + (p ^ 1) * BW, vb, tid);
        }
        __syncthreads();
        p ^= 1;
    }

    float2 bv[4];
#pragma unroll
    for (int c = 0; c < 4; c++)
        bv[c] = hasBias ? *(const float2*)(bias + cb + 32 * c + 2 * tx)
                        : make_float2(0.f, 0.f);

#pragma unroll
    for (int r = 0; r < 4; r++) {
        int row = rb + 4 * ty + r;
        float* dst = C + (size_t)row * DIMD + cb + 2 * tx;
#pragma unroll
        for (int c = 0; c < 4; c++) {
            float2 u = unpack2(acc[r][c]);
            *(float2*)(dst + 32 * c) = make_float2(u.x + bv[c].x, u.y + bv[c].y);
        }
    }
}

// ---------------- streaming attention stats: per row -> (p = 1/sumexp, argmax)
__global__ __launch_bounds__(512) void attn_kernel() {
    extern __shared__ float sm[];
    float* as_ = sm;
    float* bs_ = sm + 2 * AW;
    int tid = threadIdx.x, tx = tid & 15, ty = tid >> 4;
    int b = blockIdx.y, rb = blockIdx.x * 128;

    int lrow = tid >> 2, lk4 = tid & 3;       // T-loader coords

    const float* qbase = g_q + ((size_t)b * NTOK + rb + lrow) * DIMD + lk4 * 4;
    const float* kbase = g_k + ((size_t)b * NTOK + lrow) * DIMD + lk4 * 4;

    float m[4], s[4];
    int ja[4];
#pragma unroll
    for (int r = 0; r < 4; r++) { m[r] = -CUDART_INF_F; s[r] = 0.f; ja[r] = 0; }

    ull acc[4][4];
#pragma unroll
    for (int r = 0; r < 4; r++)
#pragma unroll
        for (int c = 0; c < 4; c++) acc[r][c] = 0ULL;

    float4 vq = *(const float4*)(qbase);
    float4 vk = *(const float4*)(kbase);
    sts_A_dup(as_, vq, tid);
    sts_B_fromT(bs_, vk, tid);
    __syncthreads();

    int p = 0;
    const int NIT = (NTOK / 128) * (DIMD / KC);   // 32 tiles * 16 chunks
    for (int it = 0; it < NIT; it++) {
        int nit = it + 1;
        if (nit < NIT) {
            int kk = (nit & 15) * KC;
            int jt = nit >> 4;
            vq = *(const float4*)(qbase + kk);
            vk = *(const float4*)(kbase + (size_t)jt * 128 * DIMD + kk);
        }
        const float* ap = as_ + p * AW;
        const float* bpp = bs_ + p * BW;
#pragma unroll
        for (int k = 0; k < KC; k++) mma_step(ap, bpp, k, tx, ty, acc);

        if ((it & 15) == 15) {
            int jt = it >> 4;
            int colbase = jt * 128 + 2 * tx;
#pragma unroll
            for (int r = 0; r < 4; r++) {
                float l[8];
#pragma unroll
                for (int c = 0; c < 4; c++) {
                    float2 u = unpack2(acc[r][c]);
                    l[2 * c]     = u.x * ATT_SCALE;
                    l[2 * c + 1] = u.y * ATT_SCALE;
                    acc[r][c] = 0ULL;
                }
                float tmax = l[0];
                int   targ = colbase;
#pragma unroll
                for (int i = 1; i < 8; i++) {
                    int col = colbase + 32 * (i >> 1) + (i & 1);
                    if (l[i] > tmax) { tmax = l[i]; targ = col; }
                }
#pragma unroll
                for (int o = 1; o < 16; o <<= 1) {
                    float om = __shfl_xor_sync(0xffffffffu, tmax, o);
                    int   oa = __shfl_xor_sync(0xffffffffu, targ, o);
                    if (om > tmax) { tmax = om; targ = oa; }
                }
                float nm = fmaxf(m[r], tmax);
                float tsum = 0.f;
#pragma unroll
                for (int i = 0; i < 8; i++) tsum += __expf(l[i] - nm);
#pragma unroll
                for (int o = 1; o < 16; o <<= 1)
                    tsum += __shfl_xor_sync(0xffffffffu, tsum, o);
                s[r] = s[r] * __expf(m[r] - nm) + tsum;
                if (tmax > m[r]) ja[r] = targ;
                m[r] = nm;
            }
        }

        if (nit < NIT) {
            sts_A_dup(as_ + (p ^ 1) * AW, vq, tid);
            sts_B_fromT(bs_ + (p ^ 1) * BW, vk, tid);
        }
        __syncthreads();
        p ^= 1;
    }

    if (tx == 0) {
#pragma unroll
        for (int r = 0; r < 4; r++) {
            int row = b * NTOK + rb + 4 * ty + r;
            g_p[row] = 1.0f / s[r];    // p_max = exp(m - lse) = 1/sumexp
            g_j[row] = ja[r];
        }
    }
}

// ---------------- build Z: spike rows p * x[argmax], else 0 ------------------
__global__ __launch_bounds__(256) void zbuild_kernel(const float* __restrict__ x) {
    int row = blockIdx.x;
    int b = row >> 12;                 // NTOK = 4096
    float p = g_p[row];
    int tid = threadIdx.x;
    float v = 0.f;
    if (p >= THRESH) {
        const float* src = x + ((size_t)((b << 12) + g_j[row])) * DIMD;
        v = p * src[tid];
    }
    g_z[(size_t)row * DIMD + tid] = v;
}

// -----------------------------------------------------------------------------
extern "C" void kernel_launch(void* const* d_in, const int* in_sizes, int n_in,
                              void* d_out, int out_size) {
    (void)in_sizes; (void)n_in; (void)out_size;
    const float* x  = (const float*)d_in[0];
    const float* y  = (const float*)d_in[1];
    const float* Wq = (const float*)d_in[2];
    const float* Wk = (const float*)d_in[3];
    const float* Wv = (const float*)d_in[4];
    const float* Wp = (const float*)d_in[5];
    const float* bp = (const float*)d_in[6];
    float* out = (float*)d_out;

    float *q, *k, *z, *M;
    cudaGetSymbolAddress((void**)&q, g_q);
    cudaGetSymbolAddress((void**)&k, g_k);
    cudaGetSymbolAddress((void**)&z, g_z);
    cudaGetSymbolAddress((void**)&M, g_M);

    cudaFuncSetAttribute(gemm_kernel, cudaFuncAttributeMaxDynamicSharedMemorySize, SMEM_BYTES);
    cudaFuncSetAttribute(attn_kernel, cudaFuncAttributeMaxDynamicSharedMemorySize, SMEM_BYTES);

    dim3 blk(512);
    // projections
    gemm_kernel<<<dim3(ROWS_TOTAL / 128, 2), blk, SMEM_BYTES>>>(x, Wq, q, nullptr, 0);
    gemm_kernel<<<dim3(ROWS_TOTAL / 128, 2), blk, SMEM_BYTES>>>(y, Wk, k, nullptr, 0);
    // fused projection matrix M = Wv @ Wp
    gemm_kernel<<<dim3(2, 2), blk, SMEM_BYTES>>>(Wv, Wp, M, nullptr, 0);
    // streaming softmax stats (max/argmax/sumexp) over q k^T
    attn_kernel<<<dim3(NTOK / 128, BATCH), blk, SMEM_BYTES>>>();
    // sparse spike rows
    zbuild_kernel<<<ROWS_TOTAL, 256>>>(x);
    // out = Z @ M + bp
    gemm_kernel<<<dim3(ROWS_TOTAL / 128, 2), blk, SMEM_BYTES>>>(z, M, out, bp, 1);
}

// round 11
// speedup vs baseline: 1.1444x; 1.1444x over previous
#include <cuda_runtime.h>
#include <math_constants.h>

#define DIMD 256
#define NTOK 4096
#define BATCH 4
#define ROWS_TOTAL (BATCH * NTOK)
#define ATT_SCALE 0.17677669529663687f
#define THRESH 0.6f

#define KC 8               // k-chunk depth
#define AP 260             // A dup tile pitch (words per k-row): 2*128 + 4 pad
#define BP 260             // B tile pitch (words per k-row): 256 cols + 4 pad
#define AW (KC * AP)       // words per A buffer
#define BW (KC * BP)       // words per B buffer

typedef unsigned long long ull;

// ---------------- scratch (device globals; no allocation allowed) -------------
__device__ float g_q[ROWS_TOTAL * DIMD];
__device__ float g_k[ROWS_TOTAL * DIMD];
__device__ float g_z[ROWS_TOTAL * DIMD];
__device__ float g_M[DIMD * DIMD];
__device__ float g_p[ROWS_TOTAL];
__device__ int   g_j[ROWS_TOTAL];

// ---------------- f32x2 helpers ----------------------------------------------
__device__ __forceinline__ void fma2(ull &d, ull a, ull b) {
    asm("fma.rn.f32x2 %0, %1, %2, %0;" : "+l"(d) : "l"(a), "l"(b));
}
__device__ __forceinline__ float2 unpack2(ull v) {
    unsigned lo, hi;
    asm("mov.b64 {%0, %1}, %2;" : "=r"(lo), "=r"(hi) : "l"(v));
    return make_float2(__uint_as_float(lo), __uint_as_float(hi));
}

// ============ tile layouts ====================================================
// A tile (dup): KC k-rows x AP words. Row r (0..127) of dim k stored as the
//   duplicated pair {a,a} at word  k*AP + 2*r.   (reads: LDS.128 broadcast)
// B tile: KC k-rows x BP words. Col c (0..255) at word k*BP + c.
//   (reads: LDS.64 at 2*tx + 32*j, conflict-free; stores: STS.32 conflict-free)

// ---- stores: regs -> smem (256-thread mappings)
// A/T loader: row = tid>>1 (0..127), k4 = tid&1 (dims 4*k4..4*k4+3)
__device__ __forceinline__ void sts_A_dup(float* dst, float4 v, int tid) {
    int row = tid >> 1, k4 = tid & 1;
    float* d = dst + (4 * k4) * AP + 2 * row;
    *(float2*)(d         ) = make_float2(v.x, v.x);
    *(float2*)(d + AP    ) = make_float2(v.y, v.y);
    *(float2*)(d + 2 * AP) = make_float2(v.z, v.z);
    *(float2*)(d + 3 * AP) = make_float2(v.w, v.w);
}
// B from T-pattern (key matrix rows are tile cols): idx in [0,512)
__device__ __forceinline__ void sts_B_fromT(float* dst, float4 v, int idx) {
    int col = idx >> 1, k4 = idx & 1;
    float* d = dst + (4 * k4) * BP + col;
    d[0]      = v.x;
    d[BP]     = v.y;
    d[2 * BP] = v.z;
    d[3 * BP] = v.w;
}
// B from N-pattern (weight matrix): idx in [0,512): kr = idx>>6, c4 = idx&63
__device__ __forceinline__ void sts_B_fromN(float* dst, float4 v, int idx) {
    int kr = idx >> 6, c4 = idx & 63;
    *(float4*)(dst + kr * BP + 4 * c4) = v;
}

// ---- one k-step: 8 rows x 16 cols per thread, f32x2
__device__ __forceinline__ void mma_step(const float* __restrict__ as_,
                                         const float* __restrict__ bs_,
                                         int k, int tx, int ty, ull acc[8][8]) {
    const float* kr = bs_ + k * BP + 2 * tx;
    ull B[8];
#pragma unroll
    for (int j = 0; j < 8; j++) B[j] = *(const ull*)(kr + 32 * j);

    const float* qr = as_ + k * AP + 16 * ty;
    ull A[8];
#pragma unroll
    for (int m2 = 0; m2 < 4; m2++) {
        ulonglong2 a = *(const ulonglong2*)(qr + 4 * m2);
        A[2 * m2] = a.x; A[2 * m2 + 1] = a.y;
    }
#pragma unroll
    for (int r = 0; r < 8; r++)
#pragma unroll
        for (int j = 0; j < 8; j++)
            fma2(acc[r][j], A[r], B[j]);
}

// ---------------- tiled GEMM: C[M x 256] = A[M x 256] @ B[256 x 256] (+bias) --
// CTA tile: 128 rows x 256 cols (full output width). grid.x = M/128.
__global__ __launch_bounds__(256) void gemm_kernel(const float* __restrict__ A,
                                                   const float* __restrict__ B,
                                                   float* __restrict__ C,
                                                   const float* __restrict__ bias,
                                                   int hasBias) {
    __shared__ __align__(16) float as_[2 * AW];
    __shared__ __align__(16) float bs_[2 * BW];
    int tid = threadIdx.x, tx = tid & 15, ty = tid >> 4;
    int rb = blockIdx.x * 128;

    ull acc[8][8];
#pragma unroll
    for (int r = 0; r < 8; r++)
#pragma unroll
        for (int j = 0; j < 8; j++) acc[r][j] = 0ULL;

    int arow = tid >> 1, ak4 = tid & 1;
    const float* Abase = A + (size_t)(rb + arow) * DIMD + 4 * ak4;
    // B loader: 2 float4 per thread per chunk
    int i0 = tid, i1 = tid + 256;
    const float* Bb0 = B + (size_t)(i0 >> 6) * DIMD + 4 * (i0 & 63);
    const float* Bb1 = B + (size_t)(i1 >> 6) * DIMD + 4 * (i1 & 63);

    float4 va = *(const float4*)(Abase);
    float4 vb0 = *(const float4*)(Bb0);
    float4 vb1 = *(const float4*)(Bb1);
    sts_A_dup(as_, va, tid);
    sts_B_fromN(bs_, vb0, i0);
    sts_B_fromN(bs_, vb1, i1);
    __syncthreads();

    int p = 0;
    const int NCH = DIMD / KC;          // 32 chunks
    for (int ck = 0; ck < NCH; ck++) {
        int nck = ck + 1;
        if (nck < NCH) {
            va  = *(const float4*)(Abase + nck * KC);
            vb0 = *(const float4*)(Bb0 + (size_t)nck * KC * DIMD);
            vb1 = *(const float4*)(Bb1 + (size_t)nck * KC * DIMD);
        }
        const float* ap = as_ + p * AW;
        const float* bpp = bs_ + p * BW;
#pragma unroll
        for (int k = 0; k < KC; k++) mma_step(ap, bpp, k, tx, ty, acc);
        if (nck < NCH) {
            sts_A_dup(as_ + (p ^ 1) * AW, va, tid);
            sts_B_fromN(bs_ + (p ^ 1) * BW, vb0, i0);
            sts_B_fromN(bs_ + (p ^ 1) * BW, vb1, i1);
        }
        __syncthreads();
        p ^= 1;
    }

#pragma unroll
    for (int r = 0; r < 8; r++) {
        int row = rb + 8 * ty + r;
        float* dst = C + (size_t)row * DIMD + 2 * tx;
#pragma unroll
        for (int j = 0; j < 8; j++) {
            float2 u = unpack2(acc[r][j]);
            if (hasBias) {
                float2 bv = *(const float2*)(bias + 32 * j + 2 * tx);
                u.x += bv.x; u.y += bv.y;
            }
            *(float2*)(dst + 32 * j) = u;
        }
    }
}

// ---------------- streaming attention stats: per row -> (p = 1/sumexp, argmax)
// CTA: 128 q-rows x 256 k-cols tile, streaming over 16 key tiles.
__global__ __launch_bounds__(256) void attn_kernel() {
    __shared__ __align__(16) float as_[2 * AW];
    __shared__ __align__(16) float bs_[2 * BW];
    int tid = threadIdx.x, tx = tid & 15, ty = tid >> 4;
    int b = blockIdx.y, rb = blockIdx.x * 128;

    int lrow = tid >> 1, lk4 = tid & 1;
    const float* qbase = g_q + ((size_t)b * NTOK + rb + lrow) * DIMD + 4 * lk4;
    int i0 = tid, i1 = tid + 256;
    const float* kb0 = g_k + ((size_t)b * NTOK + (i0 >> 1)) * DIMD + 4 * (i0 & 1);
    const float* kb1 = g_k + ((size_t)b * NTOK + (i1 >> 1)) * DIMD + 4 * (i1 & 1);

    float m[8], s[8];
    int ja[8];
#pragma unroll
    for (int r = 0; r < 8; r++) { m[r] = -CUDART_INF_F; s[r] = 0.f; ja[r] = 0; }

    ull acc[8][8];
#pragma unroll
    for (int r = 0; r < 8; r++)
#pragma unroll
        for (int j = 0; j < 8; j++) acc[r][j] = 0ULL;

    float4 vq  = *(const float4*)(qbase);
    float4 vk0 = *(const float4*)(kb0);
    float4 vk1 = *(const float4*)(kb1);
    sts_A_dup(as_, vq, tid);
    sts_B_fromT(bs_, vk0, i0);
    sts_B_fromT(bs_, vk1, i1);
    __syncthreads();

    int p = 0;
    const int NCH = DIMD / KC;                    // 32 chunks per key tile
    const int NIT = (NTOK / 256) * NCH;           // 16 key tiles
    for (int it = 0; it < NIT; it++) {
        int nit = it + 1;
        if (nit < NIT) {
            int kk = (nit & (NCH - 1)) * KC;
            size_t joff = (size_t)(nit >> 5) * 256 * DIMD;
            vq  = *(const float4*)(qbase + kk);
            vk0 = *(const float4*)(kb0 + joff + kk);
            vk1 = *(const float4*)(kb1 + joff + kk);
        }
        const float* ap = as_ + p * AW;
        const float* bpp = bs_ + p * BW;
#pragma unroll
        for (int k = 0; k < KC; k++) mma_step(ap, bpp, k, tx, ty, acc);

        if ((it & (NCH - 1)) == NCH - 1) {
            int jt = it >> 5;
            int colbase = jt * 256 + 2 * tx;
#pragma unroll
            for (int r = 0; r < 8; r++) {
                float l[16];
#pragma unroll
                for (int j = 0; j < 8; j++) {
                    float2 u = unpack2(acc[r][j]);
                    l[2 * j]     = u.x * ATT_SCALE;
                    l[2 * j + 1] = u.y * ATT_SCALE;
                    acc[r][j] = 0ULL;
                }
                float tmax = l[0];
                int   targ = colbase;
#pragma unroll
                for (int i = 1; i < 16; i++) {
                    int col = colbase + 32 * (i >> 1) + (i & 1);
                    if (l[i] > tmax) { tmax = l[i]; targ = col; }
                }
#pragma unroll
                for (int o = 1; o < 16; o <<= 1) {
                    float om = __shfl_xor_sync(0xffffffffu, tmax, o);
                    int   oa = __shfl_xor_sync(0xffffffffu, targ, o);
                    if (om > tmax) { tmax = om; targ = oa; }
                }
                float nm = fmaxf(m[r], tmax);
                float tsum = 0.f;
#pragma unroll
                for (int i = 0; i < 16; i++) tsum += __expf(l[i] - nm);
#pragma unroll
                for (int o = 1; o < 16; o <<= 1)
                    tsum += __shfl_xor_sync(0xffffffffu, tsum, o);
                s[r] = s[r] * __expf(m[r] - nm) + tsum;
                if (tmax > m[r]) ja[r] = targ;
                m[r] = nm;
            }
        }

        if (nit < NIT) {
            sts_A_dup(as_ + (p ^ 1) * AW, vq, tid);
            sts_B_fromT(bs_ + (p ^ 1) * BW, vk0, i0);
            sts_B_fromT(bs_ + (p ^ 1) * BW, vk1, i1);
        }
        __syncthreads();
        p ^= 1;
    }

    if (tx == 0) {
#pragma unroll
        for (int r = 0; r < 8; r++) {
            int row = b * NTOK + rb + 8 * ty + r;
            g_p[row] = 1.0f / s[r];    // p_max = exp(m - lse) = 1/sumexp
            g_j[row] = ja[r];
        }
    }
}

// ---------------- build Z: spike rows p * x[argmax], else 0 ------------------
__global__ __launch_bounds__(256) void zbuild_kernel(const float* __restrict__ x) {
    int row = blockIdx.x;
    int b = row >> 12;                 // NTOK = 4096
    float p = g_p[row];
    int tid = threadIdx.x;
    float v = 0.f;
    if (p >= THRESH) {
        const float* src = x + ((size_t)((b << 12) + g_j[row])) * DIMD;
        v = p * src[tid];
    }
    g_z[(size_t)row * DIMD + tid] = v;
}

// -----------------------------------------------------------------------------
extern "C" void kernel_launch(void* const* d_in, const int* in_sizes, int n_in,
                              void* d_out, int out_size) {
    (void)in_sizes; (void)n_in; (void)out_size;
    const float* x  = (const float*)d_in[0];
    const float* y  = (const float*)d_in[1];
    const float* Wq = (const float*)d_in[2];
    const float* Wk = (const float*)d_in[3];
    const float* Wv = (const float*)d_in[4];
    const float* Wp = (const float*)d_in[5];
    const float* bp = (const float*)d_in[6];
    float* out = (float*)d_out;

    float *q, *k, *z, *M;
    cudaGetSymbolAddress((void**)&q, g_q);
    cudaGetSymbolAddress((void**)&k, g_k);
    cudaGetSymbolAddress((void**)&z, g_z);
    cudaGetSymbolAddress((void**)&M, g_M);

    dim3 blk(256);
    // projections
    gemm_kernel<<<ROWS_TOTAL / 128, blk>>>(x, Wq, q, nullptr, 0);
    gemm_kernel<<<ROWS_TOTAL / 128, blk>>>(y, Wk, k, nullptr, 0);
    // fused projection matrix M = Wv @ Wp
    gemm_kernel<<<2, blk>>>(Wv, Wp, M, nullptr, 0);
    // streaming softmax stats (max/argmax/sumexp) over q k^T
    attn_kernel<<<dim3(NTOK / 128, BATCH), blk>>>();
    // sparse spike rows
    zbuild_kernel<<<ROWS_TOTAL, 256>>>(x);
    // out = Z @ M + bp
    gemm_kernel<<<ROWS_TOTAL / 128, blk>>>(z, M, out, bp, 1);
}

// round 15
// speedup vs baseline: 1.1456x; 1.0010x over previous
#include <cuda_runtime.h>
#include <math_constants.h>

#define DIMD 256
#define NTOK 4096
#define BATCH 4
#define ROWS_TOTAL (BATCH * NTOK)
#define ATT_SCALE 0.17677669529663687f
#define THRESH 0.6f

#define KC 8               // k-chunk depth
#define AP 260             // A dup tile pitch (words per k-row): 2*128 + 4 pad
#define BP 260             // B tile pitch (words per k-row): 256 cols + 4 pad
#define AW (KC * AP)       // words per A buffer
#define BW (KC * BP)       // words per B buffer

// exp2 magic: bits(Y)+KADD (mod 2^32), <<23  ==  (i+127)<<23
#define KADD (127u - 0x4B400000u)

typedef unsigned long long ull;

// ---------------- scratch (device globals; no allocation allowed) -------------
__device__ float g_q[ROWS_TOTAL * DIMD];
__device__ float g_k[ROWS_TOTAL * DIMD];
__device__ float g_z[ROWS_TOTAL * DIMD];
__device__ float g_M[DIMD * DIMD];
__device__ float g_p[ROWS_TOTAL];
__device__ int   g_j[ROWS_TOTAL];

// ---------------- f32x2 helpers ----------------------------------------------
__device__ __forceinline__ void fma2(ull &d, ull a, ull b) {
    asm("fma.rn.f32x2 %0, %1, %2, %0;" : "+l"(d) : "l"(a), "l"(b));
}
__device__ __forceinline__ ull fma2v(ull a, ull b, ull c) {
    ull d;
    asm("fma.rn.f32x2 %0, %1, %2, %3;" : "=l"(d) : "l"(a), "l"(b), "l"(c));
    return d;
}
__device__ __forceinline__ ull mul2(ull a, ull b) {
    ull d;
    asm("mul.rn.f32x2 %0, %1, %2;" : "=l"(d) : "l"(a), "l"(b));
    return d;
}
__device__ __forceinline__ ull add2(ull a, ull b) {
    ull d;
    asm("add.rn.f32x2 %0, %1, %2;" : "=l"(d) : "l"(a), "l"(b));
    return d;
}
__device__ __forceinline__ float2 unpack2(ull v) {
    unsigned lo, hi;
    asm("mov.b64 {%0, %1}, %2;" : "=r"(lo), "=r"(hi) : "l"(v));
    return make_float2(__uint_as_float(lo), __uint_as_float(hi));
}
__device__ __forceinline__ ull pack_dup(float x) {
    ull d;
    asm("mov.b64 %0, {%1, %1};" : "=l"(d) : "r"(__float_as_uint(x)));
    return d;
}
__device__ __forceinline__ ull pack2u(unsigned lo, unsigned hi) {
    ull d;
    asm("mov.b64 %0, {%1, %2};" : "=l"(d) : "r"(lo), "r"(hi));
    return d;
}

// ============ tile layouts ====================================================
// A tile (dup): KC k-rows x AP words. Row r (0..127) of dim k stored as the
//   duplicated pair {a,a} at word  k*AP + 2*r.   (reads: LDS.128 broadcast)
// B tile: KC k-rows x BP words. Col c (0..255) at word k*BP + c.

// ---- stores: regs -> smem (256-thread mappings)
__device__ __forceinline__ void sts_A_dup(float* dst, float4 v, int tid) {
    int row = tid >> 1, k4 = tid & 1;
    float* d = dst + (4 * k4) * AP + 2 * row;
    *(float2*)(d         ) = make_float2(v.x, v.x);
    *(float2*)(d + AP    ) = make_float2(v.y, v.y);
    *(float2*)(d + 2 * AP) = make_float2(v.z, v.z);
    *(float2*)(d + 3 * AP) = make_float2(v.w, v.w);
}
__device__ __forceinline__ void sts_B_fromT(float* dst, float4 v, int idx) {
    int col = idx >> 1, k4 = idx & 1;
    float* d = dst + (4 * k4) * BP + col;
    d[0]      = v.x;
    d[BP]     = v.y;
    d[2 * BP] = v.z;
    d[3 * BP] = v.w;
}
__device__ __forceinline__ void sts_B_fromN(float* dst, float4 v, int idx) {
    int kr = idx >> 6, c4 = idx & 63;
    *(float4*)(dst + kr * BP + 4 * c4) = v;
}

// ---- one k-step: 8 rows x 16 cols per thread, f32x2
__device__ __forceinline__ void mma_step(const float* __restrict__ as_,
                                         const float* __restrict__ bs_,
                                         int k, int tx, int ty, ull acc[8][8]) {
    const float* kr = bs_ + k * BP + 2 * tx;
    ull B[8];
#pragma unroll
    for (int j = 0; j < 8; j++) B[j] = *(const ull*)(kr + 32 * j);

    const float* qr = as_ + k * AP + 16 * ty;
    ull A[8];
#pragma unroll
    for (int m2 = 0; m2 < 4; m2++) {
        ulonglong2 a = *(const ulonglong2*)(qr + 4 * m2);
        A[2 * m2] = a.x; A[2 * m2 + 1] = a.y;
    }
#pragma unroll
    for (int r = 0; r < 8; r++)
#pragma unroll
        for (int j = 0; j < 8; j++)
            fma2(acc[r][j], A[r], B[j]);
}

// ---------------- tiled GEMM: C[M x 256] = A[M x 256] @ B[256 x 256] (+bias) --
__global__ __launch_bounds__(256) void gemm_kernel(const float* __restrict__ A,
                                                   const float* __restrict__ B,
                                                   float* __restrict__ C,
                                                   const float* __restrict__ bias,
                                                   int hasBias) {
    __shared__ __align__(16) float as_[2 * AW];
    __shared__ __align__(16) float bs_[2 * BW];
    int tid = threadIdx.x, tx = tid & 15, ty = tid >> 4;
    int rb = blockIdx.x * 128;

    ull acc[8][8];
#pragma unroll
    for (int r = 0; r < 8; r++)
#pragma unroll
        for (int j = 0; j < 8; j++) acc[r][j] = 0ULL;

    int arow = tid >> 1, ak4 = tid & 1;
    const float* Abase = A + (size_t)(rb + arow) * DIMD + 4 * ak4;
    int i0 = tid, i1 = tid + 256;
    const float* Bb0 = B + (size_t)(i0 >> 6) * DIMD + 4 * (i0 & 63);
    const float* Bb1 = B + (size_t)(i1 >> 6) * DIMD + 4 * (i1 & 63);

    float4 va = *(const float4*)(Abase);
    float4 vb0 = *(const float4*)(Bb0);
    float4 vb1 = *(const float4*)(Bb1);
    sts_A_dup(as_, va, tid);
    sts_B_fromN(bs_, vb0, i0);
    sts_B_fromN(bs_, vb1, i1);
    __syncthreads();

    int p = 0;
    const int NCH = DIMD / KC;          // 32 chunks
    for (int ck = 0; ck < NCH; ck++) {
        int nck = ck + 1;
        if (nck < NCH) {
            va  = *(const float4*)(Abase + nck * KC);
            vb0 = *(const float4*)(Bb0 + (size_t)nck * KC * DIMD);
            vb1 = *(const float4*)(Bb1 + (size_t)nck * KC * DIMD);
        }
        const float* ap = as_ + p * AW;
        const float* bpp = bs_ + p * BW;
#pragma unroll
        for (int k = 0; k < KC; k++) mma_step(ap, bpp, k, tx, ty, acc);
        if (nck < NCH) {
            sts_A_dup(as_ + (p ^ 1) * AW, va, tid);
            sts_B_fromN(bs_ + (p ^ 1) * BW, vb0, i0);
            sts_B_fromN(bs_ + (p ^ 1) * BW, vb1, i1);
        }
        __syncthreads();
        p ^= 1;
    }

#pragma unroll
    for (int r = 0; r < 8; r++) {
        int row = rb + 8 * ty + r;
        float* dst = C + (size_t)row * DIMD + 2 * tx;
#pragma unroll
        for (int j = 0; j < 8; j++) {
            float2 u = unpack2(acc[r][j]);
            if (hasBias) {
                float2 bv = *(const float2*)(bias + 32 * j + 2 * tx);
                u.x += bv.x; u.y += bv.y;
            }
            *(float2*)(dst + 32 * j) = u;
        }
    }
}

// ---------------- streaming attention stats: per row -> (p = 1/sumexp, argmax)
// No online max rescale: logits bounded (|l| < ~20), so s = sum(exp(l)) direct.
// exp computed as packed f32x2 polynomial 2^(raw*C) on the FMA pipe (no MUFU).
__global__ __launch_bounds__(256) void attn_kernel() {
    __shared__ __align__(16) float as_[2 * AW];
    __shared__ __align__(16) float bs_[2 * BW];
    int tid = threadIdx.x, tx = tid & 15, ty = tid >> 4;
    int b = blockIdx.y, rb = blockIdx.x * 128;

    int lrow = tid >> 1, lk4 = tid & 1;
    const float* qbase = g_q + ((size_t)b * NTOK + rb + lrow) * DIMD + 4 * lk4;
    int i0 = tid, i1 = tid + 256;
    const float* kb0 = g_k + ((size_t)b * NTOK + (i0 >> 1)) * DIMD + 4 * (i0 & 1);
    const float* kb1 = g_k + ((size_t)b * NTOK + (i1 >> 1)) * DIMD + 4 * (i1 & 1);

    float m[8], s[8];
    int ja[8];
#pragma unroll
    for (int r = 0; r < 8; r++) { m[r] = -CUDART_INF_F; s[r] = 0.f; ja[r] = 0; }

    ull acc[8][8];
#pragma unroll
    for (int r = 0; r < 8; r++)
#pragma unroll
        for (int j = 0; j < 8; j++) acc[r][j] = 0ULL;

    float4 vq  = *(const float4*)(qbase);
    float4 vk0 = *(const float4*)(kb0);
    float4 vk1 = *(const float4*)(kb1);
    sts_A_dup(as_, vq, tid);
    sts_B_fromT(bs_, vk0, i0);
    sts_B_fromT(bs_, vk1, i1);
    __syncthreads();

    int p = 0;
    const int NCH = DIMD / KC;                    // 32 chunks per key tile
    const int NIT = (NTOK / 256) * NCH;           // 16 key tiles
    for (int it = 0; it < NIT; it++) {
        int nit = it + 1;
        if (nit < NIT) {
            int kk = (nit & (NCH - 1)) * KC;
            size_t joff = (size_t)(nit >> 5) * 256 * DIMD;
            vq  = *(const float4*)(qbase + kk);
            vk0 = *(const float4*)(kb0 + joff + kk);
            vk1 = *(const float4*)(kb1 + joff + kk);
        }
        const float* ap = as_ + p * AW;
        const float* bpp = bs_ + p * BW;
#pragma unroll
        for (int k = 0; k < KC; k++) mma_step(ap, bpp, k, tx, ty, acc);

        // stage next chunk first so vq/vk are dead during the epilogue
        if (nit < NIT) {
            sts_A_dup(as_ + (p ^ 1) * AW, vq, tid);
            sts_B_fromT(bs_ + (p ^ 1) * BW, vk0, i0);
            sts_B_fromT(bs_ + (p ^ 1) * BW, vk1, i1);
        }

        if ((it & (NCH - 1)) == NCH - 1) {
            // ------- per-tile softmax stats epilogue (raw logits in acc) -------
            const ull C2   = pack_dup((float)(0.17677669529663687 * 1.4426950408889634));
            const ull MAGP = pack_dup(12582912.0f);    //  1.5 * 2^23
            const ull MAGN = pack_dup(-12582912.0f);
            const ull NEG1 = pack_dup(-1.0f);
            const ull P6 = pack_dup(1.5403530393381606e-4f);
            const ull P5 = pack_dup(1.3333558146428443e-3f);
            const ull P4 = pack_dup(9.618129107628477e-3f);
            const ull P3 = pack_dup(5.550410866482158e-2f);
            const ull P2 = pack_dup(2.402265069591007e-1f);
            const ull P1 = pack_dup(6.931471805599453e-1f);
            const ull P0 = pack_dup(1.0f);
            int jt = it >> 5;
            int colbase = jt * 256 + 2 * tx;
#pragma unroll
            for (int r = 0; r < 8; r++) {
                // max/argmax over the 16 raw logits this thread owns in row r
                float tmax = -CUDART_INF_F;
                int   targ = 0;
#pragma unroll
                for (int j = 0; j < 8; j++) {
                    float2 u = unpack2(acc[r][j]);
                    int c0 = colbase + 32 * j;
                    if (u.x > tmax) { tmax = u.x; targ = c0; }
                    if (u.y > tmax) { tmax = u.y; targ = c0 + 1; }
                }
#pragma unroll
                for (int o = 1; o < 16; o <<= 1) {
                    float om = __shfl_xor_sync(0xffffffffu, tmax, o);
                    int   oa = __shfl_xor_sync(0xffffffffu, targ, o);
                    if (om > tmax) { tmax = om; targ = oa; }
                }
                if (tmax > m[r]) { m[r] = tmax; ja[r] = targ; }

                // packed poly exp2: sum += 2^(raw * C)  (FMA pipe, zero MUFU)
                ull sum2 = 0ULL;
#pragma unroll
                for (int j = 0; j < 8; j++) {
                    ull y = mul2(acc[r][j], C2);
                    acc[r][j] = 0ULL;
                    ull Y = add2(y, MAGP);            // round-to-int magic
                    ull t = add2(Y, MAGN);            // t = round(y)
                    ull f = fma2v(t, NEG1, y);        // f = y - t, f in [-0.5,0.5]
                    ull pl = fma2v(f, P6, P5);
                    pl = fma2v(pl, f, P4);
                    pl = fma2v(pl, f, P3);
                    pl = fma2v(pl, f, P2);
                    pl = fma2v(pl, f, P1);
                    pl = fma2v(pl, f, P0);            // pl = 2^f
                    unsigned ylo, yhi;
                    asm("mov.b64 {%0, %1}, %2;" : "=r"(ylo), "=r"(yhi) : "l"(Y));
                    unsigned s0 = (ylo + KADD) << 23; // (i+127)<<23 = bits(2^i)
                    unsigned s1 = (yhi + KADD) << 23;
                    ull sc = pack2u(s0, s1);
                    sum2 = fma2v(pl, sc, sum2);       // sum += 2^f * 2^i
                }
                float2 ts = unpack2(sum2);
                float tsum = ts.x + ts.y;
#pragma unroll
                for (int o = 1; o < 16; o <<= 1)
                    tsum += __shfl_xor_sync(0xffffffffu, tsum, o);
                s[r] += tsum;
            }
        }

        __syncthreads();
        p ^= 1;
    }

    if (tx == 0) {
#pragma unroll
        for (int r = 0; r < 8; r++) {
            int row = b * NTOK + rb + 8 * ty + r;
            // p_max = exp(m)/sum(exp(l)) ; 2^(m*C) == exp(m*ATT_SCALE)
            g_p[row] = exp2f(m[r] * (float)(0.17677669529663687 * 1.4426950408889634)) / s[r];
            g_j[row] = ja[r];
        }
    }
}

// ---------------- build Z: spike rows p * x[argmax], else 0 ------------------
__global__ __launch_bounds__(256) void zbuild_kernel(const float* __restrict__ x) {
    int row = blockIdx.x;
    int b = row >> 12;                 // NTOK = 4096
    float p = g_p[row];
    int tid = threadIdx.x;
    float v = 0.f;
    if (p >= THRESH) {
        const float* src = x + ((size_t)((b << 12) + g_j[row])) * DIMD;
        v = p * src[tid];
    }
    g_z[(size_t)row * DIMD + tid] = v;
}

// -----------------------------------------------------------------------------
extern "C" void kernel_launch(void* const* d_in, const int* in_sizes, int n_in,
                              void* d_out, int out_size) {
    (void)in_sizes; (void)n_in; (void)out_size;
    const float* x  = (const float*)d_in[0];
    const float* y  = (const float*)d_in[1];
    const float* Wq = (const float*)d_in[2];
    const float* Wk = (const float*)d_in[3];
    const float* Wv = (const float*)d_in[4];
    const float* Wp = (const float*)d_in[5];
    const float* bp = (const float*)d_in[6];
    float* out = (float*)d_out;

    float *q, *k, *z, *M;
    cudaGetSymbolAddress((void**)&q, g_q);
    cudaGetSymbolAddress((void**)&k, g_k);
    cudaGetSymbolAddress((void**)&z, g_z);
    cudaGetSymbolAddress((void**)&M, g_M);

    dim3 blk(256);
    // projections
    gemm_kernel<<<ROWS_TOTAL / 128, blk>>>(x, Wq, q, nullptr, 0);
    gemm_kernel<<<ROWS_TOTAL / 128, blk>>>(y, Wk, k, nullptr, 0);
    // fused projection matrix M = Wv @ Wp
    gemm_kernel<<<2, blk>>>(Wv, Wp, M, nullptr, 0);
    // streaming softmax stats (max/argmax/sumexp) over q k^T
    attn_kernel<<<dim3(NTOK / 128, BATCH), blk>>>();
    // sparse spike rows
    zbuild_kernel<<<ROWS_TOTAL, 256>>>(x);
    // out = Z @ M + bp
    gemm_kernel<<<ROWS_TOTAL / 128, blk>>>(z, M, out, bp, 1);
}

// round 17
// speedup vs baseline: 1.6379x; 1.4298x over previous
#include <cuda_runtime.h>
#include <cuda_fp16.h>
#include <math_constants.h>
#include <cstdint>

#define DIMD 256
#define NTOK 4096
#define BATCH 4
#define ROWS_TOTAL (BATCH * NTOK)
#define ATT_SCALE 0.17677669529663687f
#define THRESH 0.6f
#define KHL 768            // widened fp16 K: [hi, lo|hi, hi|lo]

typedef unsigned long long ull;

// ---------------- scratch (device globals; no allocation allowed) -------------
__device__ __half g_qa[(size_t)ROWS_TOTAL * KHL];   // [qh, ql, qh]
__device__ __half g_kb[(size_t)ROWS_TOTAL * KHL];   // [kh, kh, kl]
__device__ float  g_z[ROWS_TOTAL * DIMD];
__device__ float  g_M[DIMD * DIMD];
__device__ float  g_p[ROWS_TOTAL];
__device__ int    g_j[ROWS_TOTAL];

// ---------------- f32x2 helpers (CUDA-core GEMM) ------------------------------
__device__ __forceinline__ void fma2(ull &d, ull a, ull b) {
    asm("fma.rn.f32x2 %0, %1, %2, %0;" : "+l"(d) : "l"(a), "l"(b));
}
__device__ __forceinline__ float2 unpack2(ull v) {
    unsigned lo, hi;
    asm("mov.b64 {%0, %1}, %2;" : "=r"(lo), "=r"(hi) : "l"(v));
    return make_float2(__uint_as_float(lo), __uint_as_float(hi));
}

// =================== FFMA2 GEMM (proven R11/R15 machinery) ====================
#define KCG 8
#define APG 260
#define BPG 260
#define AWG (KCG * APG)
#define BWG (KCG * BPG)

__device__ __forceinline__ void sts_A_dup(float* dst, float4 v, int tid) {
    int row = tid >> 1, k4 = tid & 1;
    float* d = dst + (4 * k4) * APG + 2 * row;
    *(float2*)(d          ) = make_float2(v.x, v.x);
    *(float2*)(d + APG    ) = make_float2(v.y, v.y);
    *(float2*)(d + 2 * APG) = make_float2(v.z, v.z);
    *(float2*)(d + 3 * APG) = make_float2(v.w, v.w);
}
__device__ __forceinline__ void sts_B_fromN(float* dst, float4 v, int idx) {
    int kr = idx >> 6, c4 = idx & 63;
    *(float4*)(dst + kr * BPG + 4 * c4) = v;
}
__device__ __forceinline__ void mma_step(const float* __restrict__ as_,
                                         const float* __restrict__ bs_,
                                         int k, int tx, int ty, ull acc[8][8]) {
    const float* kr = bs_ + k * BPG + 2 * tx;
    ull B[8];
#pragma unroll
    for (int j = 0; j < 8; j++) B[j] = *(const ull*)(kr + 32 * j);
    const float* qr = as_ + k * APG + 16 * ty;
    ull A[8];
#pragma unroll
    for (int m2 = 0; m2 < 4; m2++) {
        ulonglong2 a = *(const ulonglong2*)(qr + 4 * m2);
        A[2 * m2] = a.x; A[2 * m2 + 1] = a.y;
    }
#pragma unroll
    for (int r = 0; r < 8; r++)
#pragma unroll
        for (int j = 0; j < 8; j++)
            fma2(acc[r][j], A[r], B[j]);
}

// mode 0: fp32 out (+bias). mode 1: q split [hi,lo,hi]. mode 2: k split [hi,hi,lo].
__global__ __launch_bounds__(256) void gemm_kernel(const float* __restrict__ A,
                                                   const float* __restrict__ B,
                                                   float* __restrict__ C,
                                                   const float* __restrict__ bias,
                                                   int hasBias,
                                                   __half* __restrict__ hout,
                                                   int mode) {
    __shared__ __align__(16) float as_[2 * AWG];
    __shared__ __align__(16) float bs_[2 * BWG];
    int tid = threadIdx.x, tx = tid & 15, ty = tid >> 4;
    int rb = blockIdx.x * 128;

    ull acc[8][8];
#pragma unroll
    for (int r = 0; r < 8; r++)
#pragma unroll
        for (int j = 0; j < 8; j++) acc[r][j] = 0ULL;

    int arow = tid >> 1, ak4 = tid & 1;
    const float* Abase = A + (size_t)(rb + arow) * DIMD + 4 * ak4;
    int i0 = tid, i1 = tid + 256;
    const float* Bb0 = B + (size_t)(i0 >> 6) * DIMD + 4 * (i0 & 63);
    const float* Bb1 = B + (size_t)(i1 >> 6) * DIMD + 4 * (i1 & 63);

    float4 va = *(const float4*)(Abase);
    float4 vb0 = *(const float4*)(Bb0);
    float4 vb1 = *(const float4*)(Bb1);
    sts_A_dup(as_, va, tid);
    sts_B_fromN(bs_, vb0, i0);
    sts_B_fromN(bs_, vb1, i1);
    __syncthreads();

    int p = 0;
    const int NCH = DIMD / KCG;
    for (int ck = 0; ck < NCH; ck++) {
        int nck = ck + 1;
        if (nck < NCH) {
            va  = *(const float4*)(Abase + nck * KCG);
            vb0 = *(const float4*)(Bb0 + (size_t)nck * KCG * DIMD);
            vb1 = *(const float4*)(Bb1 + (size_t)nck * KCG * DIMD);
        }
        const float* ap = as_ + p * AWG;
        const float* bpp = bs_ + p * BWG;
#pragma unroll
        for (int k = 0; k < KCG; k++) mma_step(ap, bpp, k, tx, ty, acc);
        if (nck < NCH) {
            sts_A_dup(as_ + (p ^ 1) * AWG, va, tid);
            sts_B_fromN(bs_ + (p ^ 1) * BWG, vb0, i0);
            sts_B_fromN(bs_ + (p ^ 1) * BWG, vb1, i1);
        }
        __syncthreads();
        p ^= 1;
    }

#pragma unroll
    for (int r = 0; r < 8; r++) {
        int row = rb + 8 * ty + r;
        if (mode == 0) {
            float* dst = C + (size_t)row * DIMD + 2 * tx;
#pragma unroll
            for (int j = 0; j < 8; j++) {
                float2 u = unpack2(acc[r][j]);
                if (hasBias) {
                    float2 bv = *(const float2*)(bias + 32 * j + 2 * tx);
                    u.x += bv.x; u.y += bv.y;
                }
                *(float2*)(dst + 32 * j) = u;
            }
        } else {
            __half* dst = hout + (size_t)row * KHL + 2 * tx;
#pragma unroll
            for (int j = 0; j < 8; j++) {
                float2 u = unpack2(acc[r][j]);
                __half hx = __float2half_rn(u.x);
                __half hy = __float2half_rn(u.y);
                __half lx = __float2half_rn(u.x - __half2float(hx));
                __half ly = __float2half_rn(u.y - __half2float(hy));
                __half2 hi2 = __halves2half2(hx, hy);
                __half2 lo2 = __halves2half2(lx, ly);
                int c = 32 * j;
                if (mode == 1) {           // q: [hi, lo, hi]
                    *(__half2*)(dst + c)       = hi2;
                    *(__half2*)(dst + 256 + c) = lo2;
                    *(__half2*)(dst + 512 + c) = hi2;
                } else {                    // k: [hi, hi, lo]
                    *(__half2*)(dst + c)       = hi2;
                    *(__half2*)(dst + 256 + c) = hi2;
                    *(__half2*)(dst + 512 + c) = lo2;
                }
            }
        }
    }
}

// =================== HMMA (mma.sync) attention ================================
// CTA: 128 threads = 4 warps (wm = wid&1 rows, wn = wid>>1 cols), warp tile 64x64.
// Q resident: 12 chunks of [128 rows x 64 halfs] = 192KB. B double-buffered 2x16KB.
// Word (=2 halfs) layout per chunk: widx = row*32 + (w ^ ((row&7)<<2)).
#define QWORDS (12 * 4096)
#define ATTN_SMEM (QWORDS * 4 + 2 * 4096 * 4 + 3072)

__device__ __forceinline__ void hmma(float* d, unsigned a0, unsigned a1,
                                     unsigned a2, unsigned a3,
                                     unsigned b0, unsigned b1) {
    asm volatile(
        "mma.sync.aligned.m16n8k16.row.col.f32.f16.f16.f32 "
        "{%0,%1,%2,%3}, {%4,%5,%6,%7}, {%8,%9}, {%0,%1,%2,%3};"
        : "+f"(d[0]), "+f"(d[1]), "+f"(d[2]), "+f"(d[3])
        : "r"(a0), "r"(a1), "r"(a2), "r"(a3), "r"(b0), "r"(b1));
}

__global__ void __launch_bounds__(128) attn_mma_kernel() {
    extern __shared__ __align__(16) unsigned smw[];
    unsigned* Qw = smw;                          // 12*4096 words
    unsigned* Bw = smw + QWORDS;                 // 2*4096 words
    float* st_max = (float*)(smw + QWORDS + 2 * 4096);
    int*   st_arg = (int*)(st_max + 256);
    float* st_sum = (float*)(st_arg + 256);

    int tid = threadIdx.x, wid = tid >> 5, lane = tid & 31;
    int wm = wid & 1, wn = wid >> 1;
    int g = lane >> 2, tc = lane & 3;
    int swz = (g & 7) << 2;
    int b = blockIdx.y, rb = blockIdx.x * 128;

    const __half* qa = g_qa + (size_t)(b * NTOK + rb) * KHL;
    const __half* kb = g_kb + (size_t)b * NTOK * KHL;

    // stage resident Q (12 chunks), swizzled
    {
        int srow = tid * 32, sw2 = (tid & 7) << 2;
        for (int c = 0; c < 12; c++) {
            const uint4* src = (const uint4*)(qa + (size_t)tid * KHL + c * 64);
#pragma unroll
            for (int u = 0; u < 8; u++)
                *(uint4*)(Qw + c * 4096 + srow + ((4 * u) ^ sw2)) = src[u];
        }
    }

    float m_run = -CUDART_INF_F, s_run = 0.f;
    int j_run = 0;

    float acc[4][8][4];
#pragma unroll
    for (int mt = 0; mt < 4; mt++)
#pragma unroll
        for (int nt = 0; nt < 8; nt++)
#pragma unroll
            for (int e = 0; e < 4; e++) acc[mt][nt][e] = 0.f;

    int rowA[4], tokB[8];
#pragma unroll
    for (int mt = 0; mt < 4; mt++) rowA[mt] = (wm * 64 + mt * 16 + g) * 32;
#pragma unroll
    for (int nt = 0; nt < 8; nt++) tokB[nt] = (wn * 64 + nt * 8 + g) * 32;

    int sbase = tid * 32, ssw = (tid & 7) << 2;

    // preload + stage B chunk 0 (tile 0)
    uint4 pv[8];
    {
        const uint4* src = (const uint4*)(kb + (size_t)tid * KHL);
#pragma unroll
        for (int u = 0; u < 8; u++) pv[u] = src[u];
#pragma unroll
        for (int u = 0; u < 8; u++)
            *(uint4*)(Bw + sbase + ((4 * u) ^ ssw)) = pv[u];
    }
    __syncthreads();

    const int NIT = 32 * 12;
    for (int it = 0; it < NIT; it++) {
        int p = it & 1;
        if (it + 1 < NIT) {
            int n1 = it + 1, kt1 = n1 / 12, c1 = n1 % 12;
            const uint4* src = (const uint4*)(kb + (size_t)(kt1 * 128 + tid) * KHL + c1 * 64);
#pragma unroll
            for (int u = 0; u < 8; u++) pv[u] = src[u];
        }
        const unsigned* Qc = Qw + (it % 12) * 4096;
        const unsigned* Bc = Bw + p * 4096;
#pragma unroll
        for (int kk = 0; kk < 4; kk++) {
            int wlo = (kk * 8 + tc) ^ swz;
            int whi = wlo ^ 4;
            unsigned a[4][4];
#pragma unroll
            for (int mt = 0; mt < 4; mt++) {
                a[mt][0] = Qc[rowA[mt] + wlo];
                a[mt][1] = Qc[rowA[mt] + 256 + wlo];   // row+8
                a[mt][2] = Qc[rowA[mt] + whi];
                a[mt][3] = Qc[rowA[mt] + 256 + whi];
            }
#pragma unroll
            for (int nt = 0; nt < 8; nt++) {
                unsigned b0 = Bc[tokB[nt] + wlo];
                unsigned b1 = Bc[tokB[nt] + whi];
#pragma unroll
                for (int mt = 0; mt < 4; mt++)
                    hmma(acc[mt][nt], a[mt][0], a[mt][1], a[mt][2], a[mt][3], b0, b1);
            }
        }

        if ((it % 12) == 11) {
            // ---- per-key-tile softmax stats epilogue ----
            int kt = it / 12;
            int colb = kt * 128 + wn * 64 + 2 * tc;
#pragma unroll
            for (int mt = 0; mt < 4; mt++)
#pragma unroll
            for (int pp = 0; pp < 2; pp++) {
                float mx = -CUDART_INF_F; int ax = 0; float sm = 0.f;
#pragma unroll
                for (int nt = 0; nt < 8; nt++) {
                    float v0 = acc[mt][nt][2 * pp];
                    float v1 = acc[mt][nt][2 * pp + 1];
                    acc[mt][nt][2 * pp] = 0.f;
                    acc[mt][nt][2 * pp + 1] = 0.f;
                    int c0 = colb + nt * 8;
                    if (v0 > mx) { mx = v0; ax = c0; }
                    if (v1 > mx) { mx = v1; ax = c0 + 1; }
                    sm += __expf(v0 * ATT_SCALE) + __expf(v1 * ATT_SCALE);
                }
#pragma unroll
                for (int o = 1; o < 4; o <<= 1) {
                    float om = __shfl_xor_sync(0xffffffffu, mx, o);
                    int   oa = __shfl_xor_sync(0xffffffffu, ax, o);
                    float os = __shfl_xor_sync(0xffffffffu, sm, o);
                    sm += os;
                    if (om > mx || (om == mx && oa < ax)) { mx = om; ax = oa; }
                }
                if (tc == 0) {
                    int row = wm * 64 + mt * 16 + g + 8 * pp;
                    st_max[wn * 128 + row] = mx;
                    st_arg[wn * 128 + row] = ax;
                    st_sum[wn * 128 + row] = sm;
                }
            }
            __syncthreads();
            {
                float m0 = st_max[tid], m1 = st_max[128 + tid];
                int   a0 = st_arg[tid], a1 = st_arg[128 + tid];
                float mt_ = m0; int at_ = a0;
                if (m1 > mt_ || (m1 == mt_ && a1 < at_)) { mt_ = m1; at_ = a1; }
                s_run += st_sum[tid] + st_sum[128 + tid];
                if (mt_ > m_run) { m_run = mt_; j_run = at_; }
            }
            __syncthreads();
        }

        if (it + 1 < NIT) {
#pragma unroll
            for (int u = 0; u < 8; u++)
                *(uint4*)(Bw + (p ^ 1) * 4096 + sbase + ((4 * u) ^ ssw)) = pv[u];
        }
        __syncthreads();
    }

    {
        int row = b * NTOK + rb + tid;
        g_p[row] = __expf(m_run * ATT_SCALE) / s_run;  // p_max = exp(m - lse)
        g_j[row] = j_run;
    }
}

// ---------------- build Z: spike rows p * x[argmax], else 0 ------------------
__global__ __launch_bounds__(256) void zbuild_kernel(const float* __restrict__ x) {
    int row = blockIdx.x;
    int b = row >> 12;                 // NTOK = 4096
    float p = g_p[row];
    int tid = threadIdx.x;
    float v = 0.f;
    if (p >= THRESH) {
        const float* src = x + ((size_t)((b << 12) + g_j[row])) * DIMD;
        v = p * src[tid];
    }
    g_z[(size_t)row * DIMD + tid] = v;
}

// -----------------------------------------------------------------------------
extern "C" void kernel_launch(void* const* d_in, const int* in_sizes, int n_in,
                              void* d_out, int out_size) {
    (void)in_sizes; (void)n_in; (void)out_size;
    const float* x  = (const float*)d_in[0];
    const float* y  = (const float*)d_in[1];
    const float* Wq = (const float*)d_in[2];
    const float* Wk = (const float*)d_in[3];
    const float* Wv = (const float*)d_in[4];
    const float* Wp = (const float*)d_in[5];
    const float* bp = (const float*)d_in[6];
    float* out = (float*)d_out;

    __half *qa, *kbuf;
    float *z, *M;
    cudaGetSymbolAddress((void**)&qa, g_qa);
    cudaGetSymbolAddress((void**)&kbuf, g_kb);
    cudaGetSymbolAddress((void**)&z, g_z);
    cudaGetSymbolAddress((void**)&M, g_M);

    cudaFuncSetAttribute(attn_mma_kernel,
                         cudaFuncAttributeMaxDynamicSharedMemorySize, ATTN_SMEM);

    dim3 blk(256);
    // projections with fp16 hi/lo split epilogues
    gemm_kernel<<<ROWS_TOTAL / 128, blk>>>(x, Wq, nullptr, nullptr, 0, qa, 1);
    gemm_kernel<<<ROWS_TOTAL / 128, blk>>>(y, Wk, nullptr, nullptr, 0, kbuf, 2);
    // fused projection matrix M = Wv @ Wp
    gemm_kernel<<<2, blk>>>(Wv, Wp, M, nullptr, 0, nullptr, 0);
    // HMMA streaming softmax stats (max/argmax/sumexp) over q k^T
    attn_mma_kernel<<<dim3(NTOK / 128, BATCH), 128, ATTN_SMEM>>>();
    // sparse spike rows
    zbuild_kernel<<<ROWS_TOTAL, 256>>>(x);
    // out = Z @ M + bp
    gemm_kernel<<<ROWS_TOTAL / 128, blk>>>(z, M, out, bp, 1, nullptr, 0);
}